// round 3
// baseline (speedup 1.0000x reference)
#include <cuda_runtime.h>
#include <cstdint>
#include <cstddef>

#define N_SENT 32768
#define EMSIZE 2048
#define NCLASS 128
#define NCOLS  384   // 3 taps * 128

// Scratch (allocation-free: __device__ globals)
__device__ float g_Y[(size_t)N_SENT * NCOLS];   // stage-1 per-tap GEMM outputs
__device__ float g_H[(size_t)N_SENT * NCLASS];  // tanh hidden
__device__ float g_G[(size_t)N_SENT * NCOLS];   // stage-2 per-tap GEMM outputs

// ---------------- helpers ----------------
__device__ __forceinline__ uint32_t f2tf32(float f) {
    uint32_t u;
    asm("cvt.rna.tf32.f32 %0, %1;" : "=r"(u) : "f"(f));
    return u;
}

__device__ __forceinline__ void cp_async16(uint32_t saddr, const float* gptr) {
    asm volatile("cp.async.ca.shared.global [%0], [%1], 16;\n"
                 :: "r"(saddr), "l"(gptr));
}
__device__ __forceinline__ void cp_commit() {
    asm volatile("cp.async.commit_group;\n" ::: "memory");
}
template<int n>
__device__ __forceinline__ void cp_wait() {
    asm volatile("cp.async.wait_group %0;\n" :: "n"(n) : "memory");
}

__device__ __forceinline__ void mma_tf32(float c[4],
                                         const uint32_t a[4],
                                         const uint32_t b[2]) {
    asm volatile(
        "mma.sync.aligned.m16n8k8.row.col.f32.tf32.tf32.f32 "
        "{%0,%1,%2,%3}, {%4,%5,%6,%7}, {%8,%9}, {%0,%1,%2,%3};\n"
        : "+f"(c[0]), "+f"(c[1]), "+f"(c[2]), "+f"(c[3])
        : "r"(a[0]), "r"(a[1]), "r"(a[2]), "r"(a[3]),
          "r"(b[0]), "r"(b[1]));
}

// ---------------- GEMM: C[:, tap*128 : tap*128+128] = A[N,K] @ B_tap[K,128] ----------------
// grid = (N/128, 3), block = 256 threads (8 warps)
// Block tile: 128(M) x 128(N), K chunk = 16, double-buffered cp.async.
// smem: As[2][128][20] (padded), Bs[2][16][132] (padded) -> ~36.5 KB static.

#define KB      16
#define A_PAD   20
#define B_PAD   132
#define A_BUF   (128 * A_PAD)   // floats per buffer
#define B_BUF   (KB * B_PAD)

__device__ __forceinline__ void issue_tile(const float* __restrict__ A,
                                           const float* __restrict__ Bt,
                                           int K, int m0, int tid, int kt,
                                           uint32_t sa, uint32_t sb)
{
    // A tile: [128 m][16 k] -> 512 float4 slots / 256 threads = 2 each
    #pragma unroll
    for (int i = 0; i < 2; i++) {
        int slot = tid + i * 256;
        int m  = slot >> 2;
        int k4 = (slot & 3) << 2;
        cp_async16(sa + (uint32_t)(m * A_PAD + k4) * 4u,
                   A + (size_t)(m0 + m) * K + (size_t)kt * KB + k4);
    }
    // B tile: [16 e][128 c] -> 512 float4 slots / 256 threads = 2 each
    #pragma unroll
    for (int i = 0; i < 2; i++) {
        int slot = tid + i * 256;
        int e  = slot >> 5;
        int c4 = (slot & 31) << 2;
        cp_async16(sb + (uint32_t)(e * B_PAD + c4) * 4u,
                   Bt + (size_t)(kt * KB + e) * 128 + c4);
    }
    cp_commit();
}

__global__ void __launch_bounds__(256)
gemm_tf32_kernel(const float* __restrict__ A,
                 const float* __restrict__ B,
                 float* __restrict__ C,
                 int K)
{
    __shared__ float As[2 * A_BUF];
    __shared__ float Bs[2 * B_BUF];

    const int tid  = threadIdx.x;
    const int warp = tid >> 5;
    const int lane = tid & 31;
    const int gid  = lane >> 2;   // group of 4
    const int tig  = lane & 3;    // thread in group
    const int wm   = warp >> 1;   // 0..3 -> M
    const int wn   = warp & 1;    // 0..1 -> N

    const int m0  = blockIdx.x * 128;
    const int tap = blockIdx.y;
    const float* Bt = B + (size_t)tap * K * 128;

    float c[2][8][4];
    #pragma unroll
    for (int mi = 0; mi < 2; mi++)
        #pragma unroll
        for (int ni = 0; ni < 8; ni++)
            #pragma unroll
            for (int q = 0; q < 4; q++) c[mi][ni][q] = 0.f;

    uint32_t sA = (uint32_t)__cvta_generic_to_shared(As);
    uint32_t sB = (uint32_t)__cvta_generic_to_shared(Bs);

    const int KT = K >> 4;  // KB = 16

    issue_tile(A, Bt, K, m0, tid, 0, sA, sB);

    for (int kt = 0; kt < KT; kt++) {
        const int buf = kt & 1;
        if (kt + 1 < KT) {
            issue_tile(A, Bt, K, m0, tid, kt + 1,
                       sA + (buf ^ 1) * A_BUF * 4u,
                       sB + (buf ^ 1) * B_BUF * 4u);
            cp_wait<1>();
        } else {
            cp_wait<0>();
        }
        __syncthreads();

        const float* a_s = As + buf * A_BUF;
        const float* b_s = Bs + buf * B_BUF;

        #pragma unroll
        for (int kk = 0; kk < 2; kk++) {
            const int k0 = kk * 8 + tig;
            uint32_t af[2][4];
            #pragma unroll
            for (int mi = 0; mi < 2; mi++) {
                int r0 = wm * 32 + mi * 16 + gid;
                af[mi][0] = f2tf32(a_s[r0 * A_PAD + k0]);
                af[mi][1] = f2tf32(a_s[(r0 + 8) * A_PAD + k0]);
                af[mi][2] = f2tf32(a_s[r0 * A_PAD + k0 + 4]);
                af[mi][3] = f2tf32(a_s[(r0 + 8) * A_PAD + k0 + 4]);
            }
            uint32_t bf[8][2];
            #pragma unroll
            for (int ni = 0; ni < 8; ni++) {
                int n = wn * 64 + ni * 8 + gid;
                bf[ni][0] = f2tf32(b_s[k0 * B_PAD + n]);
                bf[ni][1] = f2tf32(b_s[(k0 + 4) * B_PAD + n]);
            }
            #pragma unroll
            for (int mi = 0; mi < 2; mi++)
                #pragma unroll
                for (int ni = 0; ni < 8; ni++)
                    mma_tf32(c[mi][ni], af[mi], bf[ni]);
        }
        __syncthreads();
    }

    // Epilogue: C row-major, ld = 384, column offset tap*128
    #pragma unroll
    for (int mi = 0; mi < 2; mi++) {
        int r0 = m0 + wm * 32 + mi * 16 + gid;
        #pragma unroll
        for (int ni = 0; ni < 8; ni++) {
            int col = tap * 128 + wn * 64 + ni * 8 + tig * 2;
            *reinterpret_cast<float2*>(&C[(size_t)r0 * NCOLS + col]) =
                make_float2(c[mi][ni][0], c[mi][ni][1]);
            *reinterpret_cast<float2*>(&C[(size_t)(r0 + 8) * NCOLS + col]) =
                make_float2(c[mi][ni][2], c[mi][ni][3]);
        }
    }
}

// ---------------- K2: causal tap combine + bias count + tanh ----------------
__global__ void combine_tanh_kernel(const float* __restrict__ Y,
                                    const float* __restrict__ b1,
                                    float* __restrict__ H)
{
    int idx = blockIdx.x * blockDim.x + threadIdx.x;
    if (idx >= N_SENT * NCLASS) return;
    int p = idx >> 7;
    int c = idx & 127;
    float s = Y[(size_t)p * NCOLS + c];
    float cnt = 1.f;
    if (p >= 1) { s += Y[(size_t)(p - 1) * NCOLS + 128 + c]; cnt = 2.f; }
    if (p >= 2) { s += Y[(size_t)(p - 2) * NCOLS + 256 + c]; cnt = 3.f; }
    H[idx] = tanhf(s + cnt * b1[c]);
}

// ---------------- K4: stage-2 combine + row<2 fallback + log_softmax ----------------
// grid = N_SENT blocks, 128 threads (one per class column)
__global__ void stage2_softmax_kernel(const float* __restrict__ G,
                                      const float* __restrict__ Y,
                                      const float* __restrict__ W2,
                                      const float* __restrict__ b1,
                                      const float* __restrict__ b2,
                                      float* __restrict__ out)
{
    const int i = blockIdx.x;
    const int c = threadIdx.x;
    __shared__ float sh[128];
    __shared__ float red[4];

    float z;
    if (i >= 2) {
        z = G[(size_t)(i - 2) * NCOLS + c]
          + G[(size_t)(i - 1) * NCOLS + 128 + c]
          + G[(size_t)i * NCOLS + 256 + c]
          + 3.0f * b2[c];
    } else {
        // fallback: Z0 = tanh(x[i]@W1[0] + b1) @ W2[0] + b2  (Y tap0 already holds x@W1[0])
        sh[c] = tanhf(Y[(size_t)i * NCOLS + c] + b1[c]);
        __syncthreads();
        float acc = b2[c];
        #pragma unroll 8
        for (int k = 0; k < 128; k++) acc += sh[k] * W2[k * 128 + c];
        z = acc;
        __syncthreads();
    }

    const int wid  = c >> 5;
    const int lane = c & 31;

    // row max
    float m = z;
    #pragma unroll
    for (int o = 16; o > 0; o >>= 1)
        m = fmaxf(m, __shfl_xor_sync(0xffffffffu, m, o));
    if (lane == 0) red[wid] = m;
    __syncthreads();
    m = fmaxf(fmaxf(red[0], red[1]), fmaxf(red[2], red[3]));
    __syncthreads();

    // row sum of exp
    float e = expf(z - m);
    float s = e;
    #pragma unroll
    for (int o = 16; o > 0; o >>= 1)
        s += __shfl_xor_sync(0xffffffffu, s, o);
    if (lane == 0) red[wid] = s;
    __syncthreads();
    s = red[0] + red[1] + red[2] + red[3];

    out[(size_t)i * NCLASS + c] = z - m - logf(s);
}

// ---------------- launch ----------------
extern "C" void kernel_launch(void* const* d_in, const int* in_sizes, int n_in,
                              void* d_out, int out_size)
{
    const float* x  = (const float*)d_in[0];  // [32768,1,2048]
    const float* W1 = (const float*)d_in[1];  // [3,2048,128]
    const float* b1 = (const float*)d_in[2];  // [1,128]
    const float* W2 = (const float*)d_in[3];  // [3,128,128]
    const float* b2 = (const float*)d_in[4];  // [1,128]
    float* out = (float*)d_out;               // [32768,1,128]

    float *Y, *H, *G;
    cudaGetSymbolAddress((void**)&Y, g_Y);
    cudaGetSymbolAddress((void**)&H, g_H);
    cudaGetSymbolAddress((void**)&G, g_G);

    dim3 gemm_grid(N_SENT / 128, 3);

    // K1: Y = x @ W1 (per tap), K = 2048
    gemm_tf32_kernel<<<gemm_grid, 256>>>(x, W1, Y, EMSIZE);

    // K2: H = tanh(shifted sum + cnt*b1)
    combine_tanh_kernel<<<(N_SENT * NCLASS) / 256, 256>>>(Y, b1, H);

    // K3: G = H @ W2 (per tap), K = 128
    gemm_tf32_kernel<<<gemm_grid, 256>>>(H, W2, G, NCLASS);

    // K4: Z combine + fallback + log_softmax
    stage2_softmax_kernel<<<N_SENT, 128>>>(G, Y, W2, b1, b2, out);
}

// round 5
// speedup vs baseline: 1.5979x; 1.5979x over previous
#include <cuda_runtime.h>
#include <cuda_fp16.h>
#include <cstdint>
#include <cstddef>

#define N_SENT 32768
#define EMSIZE 2048
#define NCLASS 128
#define NCOLS  384   // 3 taps * 128
#define TAPS   3

// ---------------- scratch (allocation-free) ----------------
__device__ float  g_Y[(size_t)N_SENT * NCOLS];
__device__ float  g_G[(size_t)N_SENT * NCOLS];
__device__ __half g_Hh[(size_t)N_SENT * NCLASS];
__device__ __half g_W1h[(size_t)TAPS * NCLASS * EMSIZE];   // [tap][c][e] K-major fp16
__device__ __half g_W2h[(size_t)TAPS * NCLASS * NCLASS];   // [tap][c][k] K-major fp16

// ---------------- PTX helpers ----------------
__device__ __forceinline__ uint32_t smem_u32(const void* p) {
    uint32_t a;
    asm("{ .reg .u64 t; cvta.to.shared.u64 t, %1; cvt.u32.u64 %0, t; }" : "=r"(a) : "l"(p));
    return a;
}
__device__ __forceinline__ void cp_async16(uint32_t saddr, const void* g) {
    asm volatile("cp.async.ca.shared.global [%0], [%1], 16;" :: "r"(saddr), "l"(g));
}
__device__ __forceinline__ void cp_commit() {
    asm volatile("cp.async.commit_group;" ::: "memory");
}
template<int n> __device__ __forceinline__ void cp_wait() {
    asm volatile("cp.async.wait_group %0;" :: "n"(n) : "memory");
}
__device__ __forceinline__ void ldsm4(uint32_t r[4], uint32_t saddr) {
    asm volatile("ldmatrix.sync.aligned.m8n8.x4.shared.b16 {%0,%1,%2,%3}, [%4];"
                 : "=r"(r[0]), "=r"(r[1]), "=r"(r[2]), "=r"(r[3]) : "r"(saddr));
}
__device__ __forceinline__ void mma16816(float d[4], const uint32_t a[4], const uint32_t b[2]) {
    asm volatile(
        "mma.sync.aligned.m16n8k16.row.col.f32.f16.f16.f32 "
        "{%0,%1,%2,%3},{%4,%5,%6,%7},{%8,%9},{%0,%1,%2,%3};"
        : "+f"(d[0]), "+f"(d[1]), "+f"(d[2]), "+f"(d[3])
        : "r"(a[0]), "r"(a[1]), "r"(a[2]), "r"(a[3]), "r"(b[0]), "r"(b[1]));
}

// Swizzled 16B-chunk offset inside a 128-row x 32-half (64B/row) tile.
// chunk c (0..3) within row: c' = c ^ ((row>>1)&3)  -> conflict-free ldmatrix + STS
__device__ __forceinline__ uint32_t tile_off(int row, int c) {
    return (uint32_t)(row * 64 + ((c ^ ((row >> 1) & 3)) << 4));
}

// ---------------- fp16 tensor-core GEMM ----------------
// C[m0:m0+128, tap*128:+128] += A[128,K] @ B_tap[K,128], fp32 accum.
// A: fp32 (converted in-kernel) or fp16; B: fp16 K-major [128 n][K].
// Block: 256 thr (8 warps, 4x2 warp grid, 32x64 warp tile). K chunk = 32.
// smem: per buffer A 8KB + B 8KB, double buffered = 32KB.

template<bool AHALF>
__global__ void __launch_bounds__(256)
gemm_fp16_kernel(const void* __restrict__ Ag,
                 const __half* __restrict__ Bg,
                 float* __restrict__ C,
                 int K)
{
    __shared__ __align__(128) uint8_t smem[2][2][8192];  // [buf][A=0,B=1]

    const int tid  = threadIdx.x;
    const int lane = tid & 31;
    const int warp = tid >> 5;
    const int wm   = warp >> 1;   // 0..3
    const int wn   = warp & 1;    // 0..1
    const int m0   = blockIdx.x * 128;
    const int tap  = blockIdx.y;
    const __half* Bt = Bg + (size_t)tap * 128 * K;
    const int KT = K >> 5;

    // per-thread load assignment: chunks i1=tid, i2=tid+256 ; row=i>>2, c=i&3
    const int lrow = tid >> 2;       // 0..63 (second chunk at +64)
    const int lc   = tid & 3;
    const uint32_t soff1 = tile_off(lrow, lc);
    const uint32_t soff2 = soff1 + 64 * 64;   // row+64 keeps same swizzle phase

    const uint32_t sbase = smem_u32(smem);
    // fragment smem offsets (within a tile)
    uint32_t aoff[2][2], boff[4][2];
    {
        const int arow0 = wm * 32 + (lane & 7) + 8 * ((lane >> 3) & 1);
        const int acadd = lane >> 4;
        const int brow0 = wn * 64 + (lane & 7) + 8 * (lane >> 4);
        const int bcadd = (lane >> 3) & 1;
        #pragma unroll
        for (int kk = 0; kk < 2; kk++) {
            #pragma unroll
            for (int mi = 0; mi < 2; mi++)
                aoff[mi][kk] = tile_off(arow0 + mi * 16, kk * 2 + acadd);
            #pragma unroll
            for (int nip = 0; nip < 4; nip++)
                boff[nip][kk] = tile_off(brow0 + nip * 16, kk * 2 + bcadd);
        }
    }

    float acc[2][8][4];
    #pragma unroll
    for (int mi = 0; mi < 2; mi++)
        #pragma unroll
        for (int ni = 0; ni < 8; ni++)
            #pragma unroll
            for (int q = 0; q < 4; q++) acc[mi][ni][q] = 0.f;

    const float*  Af = (const float*)Ag;
    const __half* Ah = (const __half*)Ag;
    __half2 st[8];  // staging for fp32->fp16 A path (two 16B chunks)

    // ---- prologue: chunk 0 ----
    {
        const int kb = 0;
        if (AHALF) {
            cp_async16(sbase + soff1, Ah + (size_t)(m0 + lrow) * K + kb + lc * 8);
            cp_async16(sbase + soff2, Ah + (size_t)(m0 + lrow + 64) * K + kb + lc * 8);
        } else {
            const float* p1 = Af + (size_t)(m0 + lrow) * K + kb + lc * 8;
            const float* p2 = Af + (size_t)(m0 + lrow + 64) * K + kb + lc * 8;
            float4 v0 = *(const float4*)p1, v1 = *(const float4*)(p1 + 4);
            float4 w0 = *(const float4*)p2, w1 = *(const float4*)(p2 + 4);
            st[0] = __floats2half2_rn(v0.x, v0.y); st[1] = __floats2half2_rn(v0.z, v0.w);
            st[2] = __floats2half2_rn(v1.x, v1.y); st[3] = __floats2half2_rn(v1.z, v1.w);
            st[4] = __floats2half2_rn(w0.x, w0.y); st[5] = __floats2half2_rn(w0.z, w0.w);
            st[6] = __floats2half2_rn(w1.x, w1.y); st[7] = __floats2half2_rn(w1.z, w1.w);
        }
        cp_async16(sbase + 8192 + soff1, Bt + (size_t)lrow * K + kb + lc * 8);
        cp_async16(sbase + 8192 + soff2, Bt + (size_t)(lrow + 64) * K + kb + lc * 8);
        cp_commit();
    }

    for (int kt = 0; kt < KT; kt++) {
        const int buf = kt & 1;
        const uint32_t sbuf = sbase + buf * 16384;

        if (!AHALF) {
            *(uint4*)(&smem[buf][0][soff1]) = *(uint4*)(&st[0]);
            *(uint4*)(&smem[buf][0][soff2]) = *(uint4*)(&st[4]);
        }

        if (kt + 1 < KT) {
            const int kb = (kt + 1) << 5;
            const uint32_t nbuf = sbase + (buf ^ 1) * 16384;
            if (AHALF) {
                cp_async16(nbuf + soff1, Ah + (size_t)(m0 + lrow) * K + kb + lc * 8);
                cp_async16(nbuf + soff2, Ah + (size_t)(m0 + lrow + 64) * K + kb + lc * 8);
            }
            cp_async16(nbuf + 8192 + soff1, Bt + (size_t)lrow * K + kb + lc * 8);
            cp_async16(nbuf + 8192 + soff2, Bt + (size_t)(lrow + 64) * K + kb + lc * 8);
            cp_commit();
            if (!AHALF) {
                const float* p1 = Af + (size_t)(m0 + lrow) * K + kb + lc * 8;
                const float* p2 = Af + (size_t)(m0 + lrow + 64) * K + kb + lc * 8;
                float4 v0 = *(const float4*)p1, v1 = *(const float4*)(p1 + 4);
                float4 w0 = *(const float4*)p2, w1 = *(const float4*)(p2 + 4);
                st[0] = __floats2half2_rn(v0.x, v0.y); st[1] = __floats2half2_rn(v0.z, v0.w);
                st[2] = __floats2half2_rn(v1.x, v1.y); st[3] = __floats2half2_rn(v1.z, v1.w);
                st[4] = __floats2half2_rn(w0.x, w0.y); st[5] = __floats2half2_rn(w0.z, w0.w);
                st[6] = __floats2half2_rn(w1.x, w1.y); st[7] = __floats2half2_rn(w1.z, w1.w);
            }
            cp_wait<1>();
        } else {
            cp_wait<0>();
        }
        __syncthreads();

        #pragma unroll
        for (int kk = 0; kk < 2; kk++) {
            uint32_t a[2][4], b[4][4];
            #pragma unroll
            for (int mi = 0; mi < 2; mi++) ldsm4(a[mi], sbuf + aoff[mi][kk]);
            #pragma unroll
            for (int nip = 0; nip < 4; nip++) ldsm4(b[nip], sbuf + 8192 + boff[nip][kk]);
            #pragma unroll
            for (int mi = 0; mi < 2; mi++)
                #pragma unroll
                for (int ni = 0; ni < 8; ni++)
                    mma16816(acc[mi][ni], a[mi], &b[ni >> 1][(ni & 1) * 2]);
        }
        __syncthreads();
    }

    // epilogue: direct float2 stores; thread (gid=lane>>2, tig=lane&3)
    const int gid = lane >> 2, tig = lane & 3;
    #pragma unroll
    for (int mi = 0; mi < 2; mi++) {
        const int r0 = m0 + wm * 32 + mi * 16 + gid;
        #pragma unroll
        for (int ni = 0; ni < 8; ni++) {
            const int col = tap * 128 + wn * 64 + ni * 8 + tig * 2;
            *(float2*)&C[(size_t)r0 * NCOLS + col]       = make_float2(acc[mi][ni][0], acc[mi][ni][1]);
            *(float2*)&C[(size_t)(r0 + 8) * NCOLS + col] = make_float2(acc[mi][ni][2], acc[mi][ni][3]);
        }
    }
}

// ---------------- weight transpose + fp16 convert: Wt[t][c][e] = (half)W[t][e][c] ----------------
__global__ void transpose_w_h_kernel(const float* __restrict__ W, __half* __restrict__ Wt,
                                     int E, int C)
{
    __shared__ float tile[32][33];
    const int t  = blockIdx.z;
    const int e0 = blockIdx.x << 5, c0 = blockIdx.y << 5;
    const float* src = W + (size_t)t * E * C;
    __half* dst = Wt + (size_t)t * C * E;
    #pragma unroll
    for (int j = 0; j < 32; j += 8)
        tile[threadIdx.y + j][threadIdx.x] =
            src[(size_t)(e0 + threadIdx.y + j) * C + c0 + threadIdx.x];
    __syncthreads();
    #pragma unroll
    for (int j = 0; j < 32; j += 8)
        dst[(size_t)(c0 + threadIdx.y + j) * E + e0 + threadIdx.x] =
            __float2half_rn(tile[threadIdx.x][threadIdx.y + j]);
}

// ---------------- combine + tanh -> fp16 H ----------------
__global__ void combine_tanh_kernel(const float4* __restrict__ Y4,
                                    const float4* __restrict__ b1_4,
                                    uint2* __restrict__ H2)
{
    int idx = blockIdx.x * blockDim.x + threadIdx.x;   // < N_SENT*32
    int p = idx >> 5, q = idx & 31;
    float4 s = Y4[(size_t)p * 96 + q];
    float cnt = 1.f;
    if (p >= 1) { float4 a = Y4[(size_t)(p - 1) * 96 + 32 + q];
                  s.x += a.x; s.y += a.y; s.z += a.z; s.w += a.w; cnt = 2.f; }
    if (p >= 2) { float4 a = Y4[(size_t)(p - 2) * 96 + 64 + q];
                  s.x += a.x; s.y += a.y; s.z += a.z; s.w += a.w; cnt = 3.f; }
    float4 b = b1_4[q];
    __half2 h01 = __floats2half2_rn(tanhf(s.x + cnt * b.x), tanhf(s.y + cnt * b.y));
    __half2 h23 = __floats2half2_rn(tanhf(s.z + cnt * b.z), tanhf(s.w + cnt * b.w));
    uint2 u;
    u.x = *reinterpret_cast<uint32_t*>(&h01);
    u.y = *reinterpret_cast<uint32_t*>(&h23);
    H2[(size_t)p * 32 + q] = u;
}

// ---------------- stage-2 combine + fallback + log_softmax (warp/row) ----------------
__global__ void stage2_softmax_kernel(const float4* __restrict__ G4,
                                      const float4* __restrict__ Y4,
                                      const float4* __restrict__ W2_4,
                                      const float4* __restrict__ b1_4,
                                      const float4* __restrict__ b2_4,
                                      float4* __restrict__ out4)
{
    const int warp = threadIdx.x >> 5, lane = threadIdx.x & 31;
    const int i = blockIdx.x * 8 + warp;
    float4 z;
    if (i >= 2) {
        float4 a = G4[(size_t)(i - 2) * 96 + lane];
        float4 b = G4[(size_t)(i - 1) * 96 + 32 + lane];
        float4 c = G4[(size_t)i * 96 + 64 + lane];
        float4 bb = b2_4[lane];
        z.x = a.x + b.x + c.x + 3.f * bb.x;
        z.y = a.y + b.y + c.y + 3.f * bb.y;
        z.z = a.z + b.z + c.z + 3.f * bb.z;
        z.w = a.w + b.w + c.w + 3.f * bb.w;
    } else {
        float4 y = Y4[(size_t)i * 96 + lane];
        float4 b1v = b1_4[lane];
        float4 h;
        h.x = tanhf(y.x + b1v.x); h.y = tanhf(y.y + b1v.y);
        h.z = tanhf(y.z + b1v.z); h.w = tanhf(y.w + b1v.w);
        float4 acc = b2_4[lane];
        for (int j = 0; j < 32; j++) {
            float hx = __shfl_sync(0xffffffffu, h.x, j);
            float hy = __shfl_sync(0xffffffffu, h.y, j);
            float hz = __shfl_sync(0xffffffffu, h.z, j);
            float hw = __shfl_sync(0xffffffffu, h.w, j);
            int k = 4 * j;
            float4 w0 = W2_4[(size_t)(k + 0) * 32 + lane];
            float4 w1 = W2_4[(size_t)(k + 1) * 32 + lane];
            float4 w2 = W2_4[(size_t)(k + 2) * 32 + lane];
            float4 w3 = W2_4[(size_t)(k + 3) * 32 + lane];
            acc.x += hx * w0.x + hy * w1.x + hz * w2.x + hw * w3.x;
            acc.y += hx * w0.y + hy * w1.y + hz * w2.y + hw * w3.y;
            acc.z += hx * w0.z + hy * w1.z + hz * w2.z + hw * w3.z;
            acc.w += hx * w0.w + hy * w1.w + hz * w2.w + hw * w3.w;
        }
        z = acc;
    }
    float m = fmaxf(fmaxf(z.x, z.y), fmaxf(z.z, z.w));
    #pragma unroll
    for (int o = 16; o > 0; o >>= 1) m = fmaxf(m, __shfl_xor_sync(0xffffffffu, m, o));
    float s = __expf(z.x - m) + __expf(z.y - m) + __expf(z.z - m) + __expf(z.w - m);
    #pragma unroll
    for (int o = 16; o > 0; o >>= 1) s += __shfl_xor_sync(0xffffffffu, s, o);
    float ls = m + __logf(s);
    out4[(size_t)i * 32 + lane] = make_float4(z.x - ls, z.y - ls, z.z - ls, z.w - ls);
}

// ---------------- launch ----------------
extern "C" void kernel_launch(void* const* d_in, const int* in_sizes, int n_in,
                              void* d_out, int out_size)
{
    const float* x  = (const float*)d_in[0];
    const float* W1 = (const float*)d_in[1];
    const float* b1 = (const float*)d_in[2];
    const float* W2 = (const float*)d_in[3];
    const float* b2 = (const float*)d_in[4];
    float* out = (float*)d_out;

    float *Y, *G; __half *Hh, *W1h, *W2h;
    cudaGetSymbolAddress((void**)&Y,   g_Y);
    cudaGetSymbolAddress((void**)&G,   g_G);
    cudaGetSymbolAddress((void**)&Hh,  g_Hh);
    cudaGetSymbolAddress((void**)&W1h, g_W1h);
    cudaGetSymbolAddress((void**)&W2h, g_W2h);

    // transpose + fp16-convert weights (K-major)
    transpose_w_h_kernel<<<dim3(EMSIZE / 32, NCLASS / 32, TAPS), dim3(32, 8)>>>(W1, W1h, EMSIZE, NCLASS);
    transpose_w_h_kernel<<<dim3(NCLASS / 32, NCLASS / 32, TAPS), dim3(32, 8)>>>(W2, W2h, NCLASS, NCLASS);

    dim3 gg(N_SENT / 128, TAPS);

    // K1: Y = x @ W1 (3 taps), K=2048, A fp32 converted in-kernel
    gemm_fp16_kernel<false><<<gg, 256>>>(x, W1h, Y, EMSIZE);

    // K2: H = tanh(shifted sum + cnt*b1) -> fp16
    combine_tanh_kernel<<<(N_SENT * 32) / 256, 256>>>(
        (const float4*)Y, (const float4*)b1, (uint2*)Hh);

    // K3: G = H @ W2 (3 taps), K=128, A fp16
    gemm_fp16_kernel<true><<<gg, 256>>>(Hh, W2h, G, NCLASS);

    // K4: Z combine + fallback + log_softmax
    stage2_softmax_kernel<<<N_SENT / 8, 256>>>(
        (const float4*)G, (const float4*)Y, (const float4*)W2,
        (const float4*)b1, (const float4*)b2, (float4*)out);
}

// round 6
// speedup vs baseline: 1.6947x; 1.0606x over previous
#include <cuda_runtime.h>
#include <cuda_fp16.h>
#include <cstdint>
#include <cstddef>

#define N_SENT 32768
#define EMSIZE 2048
#define NCLASS 128
#define NCOLS  384   // 3 taps * 128
#define TAPS   3

// ---------------- scratch (allocation-free) ----------------
__device__ float  g_Y[(size_t)N_SENT * NCOLS];
__device__ float  g_G[(size_t)N_SENT * NCOLS];
__device__ __half g_Hh[(size_t)N_SENT * NCLASS];
__device__ __half g_W1h[(size_t)TAPS * NCLASS * EMSIZE];   // [tap][c][e] K-major fp16
__device__ __half g_W2h[(size_t)TAPS * NCLASS * NCLASS];   // [tap][c][k] K-major fp16

// ---------------- PTX helpers ----------------
__device__ __forceinline__ uint32_t smem_u32(const void* p) {
    uint32_t a;
    asm("{ .reg .u64 t; cvta.to.shared.u64 t, %1; cvt.u32.u64 %0, t; }" : "=r"(a) : "l"(p));
    return a;
}
__device__ __forceinline__ void cp_async16(uint32_t saddr, const void* g) {
    asm volatile("cp.async.ca.shared.global [%0], [%1], 16;" :: "r"(saddr), "l"(g));
}
__device__ __forceinline__ void cp_commit() {
    asm volatile("cp.async.commit_group;" ::: "memory");
}
template<int n> __device__ __forceinline__ void cp_wait() {
    asm volatile("cp.async.wait_group %0;" :: "n"(n) : "memory");
}
__device__ __forceinline__ void ldsm4(uint32_t r[4], uint32_t saddr) {
    asm volatile("ldmatrix.sync.aligned.m8n8.x4.shared.b16 {%0,%1,%2,%3}, [%4];"
                 : "=r"(r[0]), "=r"(r[1]), "=r"(r[2]), "=r"(r[3]) : "r"(saddr));
}
__device__ __forceinline__ void mma16816(float d[4], const uint32_t a[4], const uint32_t b[2]) {
    asm volatile(
        "mma.sync.aligned.m16n8k16.row.col.f32.f16.f16.f32 "
        "{%0,%1,%2,%3},{%4,%5,%6,%7},{%8,%9},{%0,%1,%2,%3};"
        : "+f"(d[0]), "+f"(d[1]), "+f"(d[2]), "+f"(d[3])
        : "r"(a[0]), "r"(a[1]), "r"(a[2]), "r"(a[3]), "r"(b[0]), "r"(b[1]));
}

// Swizzled 16B-chunk offset inside a 128-row x 32-half (64B/row) tile.
__device__ __forceinline__ uint32_t tile_off(int row, int c) {
    return (uint32_t)(row * 64 + ((c ^ ((row >> 1) & 3)) << 4));
}

// ---------------- fp16 tensor-core GEMM ----------------
// Grid: 1-D, bid -> (m_tile = bid/3, tap = bid%3). Consecutive CTAs share the
// same A rows so A is fetched from DRAM once and L2-hits for the other 2 taps.
template<bool AHALF>
__global__ void __launch_bounds__(256)
gemm_fp16_kernel(const void* __restrict__ Ag,
                 const __half* __restrict__ Bg,
                 float* __restrict__ C,
                 int K)
{
    __shared__ __align__(128) uint8_t smem[2][2][8192];  // [buf][A=0,B=1]

    const int tid  = threadIdx.x;
    const int lane = tid & 31;
    const int warp = tid >> 5;
    const int wm   = warp >> 1;   // 0..3
    const int wn   = warp & 1;    // 0..1
    const int tap  = blockIdx.x % TAPS;
    const int m0   = (blockIdx.x / TAPS) * 128;
    const __half* Bt = Bg + (size_t)tap * 128 * K;
    const int KT = K >> 5;

    const int lrow = tid >> 2;       // 0..63 (second chunk at +64)
    const int lc   = tid & 3;
    const uint32_t soff1 = tile_off(lrow, lc);
    const uint32_t soff2 = soff1 + 64 * 64;

    const uint32_t sbase = smem_u32(smem);
    uint32_t aoff[2][2], boff[4][2];
    {
        const int arow0 = wm * 32 + (lane & 7) + 8 * ((lane >> 3) & 1);
        const int acadd = lane >> 4;
        const int brow0 = wn * 64 + (lane & 7) + 8 * (lane >> 4);
        const int bcadd = (lane >> 3) & 1;
        #pragma unroll
        for (int kk = 0; kk < 2; kk++) {
            #pragma unroll
            for (int mi = 0; mi < 2; mi++)
                aoff[mi][kk] = tile_off(arow0 + mi * 16, kk * 2 + acadd);
            #pragma unroll
            for (int nip = 0; nip < 4; nip++)
                boff[nip][kk] = tile_off(brow0 + nip * 16, kk * 2 + bcadd);
        }
    }

    float acc[2][8][4];
    #pragma unroll
    for (int mi = 0; mi < 2; mi++)
        #pragma unroll
        for (int ni = 0; ni < 8; ni++)
            #pragma unroll
            for (int q = 0; q < 4; q++) acc[mi][ni][q] = 0.f;

    const float*  Af = (const float*)Ag;
    const __half* Ah = (const __half*)Ag;
    __half2 st[8];

    // ---- prologue: chunk 0 ----
    {
        if (AHALF) {
            cp_async16(sbase + soff1, Ah + (size_t)(m0 + lrow) * K + lc * 8);
            cp_async16(sbase + soff2, Ah + (size_t)(m0 + lrow + 64) * K + lc * 8);
        } else {
            const float* p1 = Af + (size_t)(m0 + lrow) * K + lc * 8;
            const float* p2 = Af + (size_t)(m0 + lrow + 64) * K + lc * 8;
            float4 v0 = *(const float4*)p1, v1 = *(const float4*)(p1 + 4);
            float4 w0 = *(const float4*)p2, w1 = *(const float4*)(p2 + 4);
            st[0] = __floats2half2_rn(v0.x, v0.y); st[1] = __floats2half2_rn(v0.z, v0.w);
            st[2] = __floats2half2_rn(v1.x, v1.y); st[3] = __floats2half2_rn(v1.z, v1.w);
            st[4] = __floats2half2_rn(w0.x, w0.y); st[5] = __floats2half2_rn(w0.z, w0.w);
            st[6] = __floats2half2_rn(w1.x, w1.y); st[7] = __floats2half2_rn(w1.z, w1.w);
        }
        cp_async16(sbase + 8192 + soff1, Bt + (size_t)lrow * K + lc * 8);
        cp_async16(sbase + 8192 + soff2, Bt + (size_t)(lrow + 64) * K + lc * 8);
        cp_commit();
    }

    for (int kt = 0; kt < KT; kt++) {
        const int buf = kt & 1;
        const uint32_t sbuf = sbase + buf * 16384;

        if (!AHALF) {
            *(uint4*)(&smem[buf][0][soff1]) = *(uint4*)(&st[0]);
            *(uint4*)(&smem[buf][0][soff2]) = *(uint4*)(&st[4]);
        }

        if (kt + 1 < KT) {
            const int kb = (kt + 1) << 5;
            const uint32_t nbuf = sbase + (buf ^ 1) * 16384;
            if (AHALF) {
                cp_async16(nbuf + soff1, Ah + (size_t)(m0 + lrow) * K + kb + lc * 8);
                cp_async16(nbuf + soff2, Ah + (size_t)(m0 + lrow + 64) * K + kb + lc * 8);
            }
            cp_async16(nbuf + 8192 + soff1, Bt + (size_t)lrow * K + kb + lc * 8);
            cp_async16(nbuf + 8192 + soff2, Bt + (size_t)(lrow + 64) * K + kb + lc * 8);
            cp_commit();
            if (!AHALF) {
                const float* p1 = Af + (size_t)(m0 + lrow) * K + kb + lc * 8;
                const float* p2 = Af + (size_t)(m0 + lrow + 64) * K + kb + lc * 8;
                float4 v0 = *(const float4*)p1, v1 = *(const float4*)(p1 + 4);
                float4 w0 = *(const float4*)p2, w1 = *(const float4*)(p2 + 4);
                st[0] = __floats2half2_rn(v0.x, v0.y); st[1] = __floats2half2_rn(v0.z, v0.w);
                st[2] = __floats2half2_rn(v1.x, v1.y); st[3] = __floats2half2_rn(v1.z, v1.w);
                st[4] = __floats2half2_rn(w0.x, w0.y); st[5] = __floats2half2_rn(w0.z, w0.w);
                st[6] = __floats2half2_rn(w1.x, w1.y); st[7] = __floats2half2_rn(w1.z, w1.w);
            }
            cp_wait<1>();
        } else {
            cp_wait<0>();
        }
        __syncthreads();

        #pragma unroll
        for (int kk = 0; kk < 2; kk++) {
            uint32_t a[2][4], b[4][4];
            #pragma unroll
            for (int mi = 0; mi < 2; mi++) ldsm4(a[mi], sbuf + aoff[mi][kk]);
            #pragma unroll
            for (int nip = 0; nip < 4; nip++) ldsm4(b[nip], sbuf + 8192 + boff[nip][kk]);
            #pragma unroll
            for (int mi = 0; mi < 2; mi++)
                #pragma unroll
                for (int ni = 0; ni < 8; ni++)
                    mma16816(acc[mi][ni], a[mi], &b[ni >> 1][(ni & 1) * 2]);
        }
        __syncthreads();
    }

    // epilogue
    const int gid = lane >> 2, tig = lane & 3;
    #pragma unroll
    for (int mi = 0; mi < 2; mi++) {
        const int r0 = m0 + wm * 32 + mi * 16 + gid;
        #pragma unroll
        for (int ni = 0; ni < 8; ni++) {
            const int col = tap * 128 + wn * 64 + ni * 8 + tig * 2;
            *(float2*)&C[(size_t)r0 * NCOLS + col]       = make_float2(acc[mi][ni][0], acc[mi][ni][1]);
            *(float2*)&C[(size_t)(r0 + 8) * NCOLS + col] = make_float2(acc[mi][ni][2], acc[mi][ni][3]);
        }
    }
}

// ---------------- weight transpose + fp16 convert ----------------
__global__ void transpose_w_h_kernel(const float* __restrict__ W, __half* __restrict__ Wt,
                                     int E, int C)
{
    __shared__ float tile[32][33];
    const int t  = blockIdx.z;
    const int e0 = blockIdx.x << 5, c0 = blockIdx.y << 5;
    const float* src = W + (size_t)t * E * C;
    __half* dst = Wt + (size_t)t * C * E;
    #pragma unroll
    for (int j = 0; j < 32; j += 8)
        tile[threadIdx.y + j][threadIdx.x] =
            src[(size_t)(e0 + threadIdx.y + j) * C + c0 + threadIdx.x];
    __syncthreads();
    #pragma unroll
    for (int j = 0; j < 32; j += 8)
        dst[(size_t)(c0 + threadIdx.y + j) * E + e0 + threadIdx.x] =
            __float2half_rn(tile[threadIdx.x][threadIdx.y + j]);
}

// ---------------- combine + tanh -> fp16 H ----------------
__global__ void combine_tanh_kernel(const float4* __restrict__ Y4,
                                    const float4* __restrict__ b1_4,
                                    uint2* __restrict__ H2)
{
    int idx = blockIdx.x * blockDim.x + threadIdx.x;   // < N_SENT*32
    int p = idx >> 5, q = idx & 31;
    float4 s = Y4[(size_t)p * 96 + q];
    float cnt = 1.f;
    if (p >= 1) { float4 a = Y4[(size_t)(p - 1) * 96 + 32 + q];
                  s.x += a.x; s.y += a.y; s.z += a.z; s.w += a.w; cnt = 2.f; }
    if (p >= 2) { float4 a = Y4[(size_t)(p - 2) * 96 + 64 + q];
                  s.x += a.x; s.y += a.y; s.z += a.z; s.w += a.w; cnt = 3.f; }
    float4 b = b1_4[q];
    __half2 h01 = __floats2half2_rn(tanhf(s.x + cnt * b.x), tanhf(s.y + cnt * b.y));
    __half2 h23 = __floats2half2_rn(tanhf(s.z + cnt * b.z), tanhf(s.w + cnt * b.w));
    uint2 u;
    u.x = *reinterpret_cast<uint32_t*>(&h01);
    u.y = *reinterpret_cast<uint32_t*>(&h23);
    H2[(size_t)p * 32 + q] = u;
}

// ---------------- stage-2 combine + fallback + log_softmax (warp/row) ----------------
__global__ void stage2_softmax_kernel(const float4* __restrict__ G4,
                                      const float4* __restrict__ Y4,
                                      const float4* __restrict__ W2_4,
                                      const float4* __restrict__ b1_4,
                                      const float4* __restrict__ b2_4,
                                      float4* __restrict__ out4)
{
    const int warp = threadIdx.x >> 5, lane = threadIdx.x & 31;
    const int i = blockIdx.x * 8 + warp;
    float4 z;
    if (i >= 2) {
        float4 a = G4[(size_t)(i - 2) * 96 + lane];
        float4 b = G4[(size_t)(i - 1) * 96 + 32 + lane];
        float4 c = G4[(size_t)i * 96 + 64 + lane];
        float4 bb = b2_4[lane];
        z.x = a.x + b.x + c.x + 3.f * bb.x;
        z.y = a.y + b.y + c.y + 3.f * bb.y;
        z.z = a.z + b.z + c.z + 3.f * bb.z;
        z.w = a.w + b.w + c.w + 3.f * bb.w;
    } else {
        float4 y = Y4[(size_t)i * 96 + lane];
        float4 b1v = b1_4[lane];
        float4 h;
        h.x = tanhf(y.x + b1v.x); h.y = tanhf(y.y + b1v.y);
        h.z = tanhf(y.z + b1v.z); h.w = tanhf(y.w + b1v.w);
        float4 acc = b2_4[lane];
        for (int j = 0; j < 32; j++) {
            float hx = __shfl_sync(0xffffffffu, h.x, j);
            float hy = __shfl_sync(0xffffffffu, h.y, j);
            float hz = __shfl_sync(0xffffffffu, h.z, j);
            float hw = __shfl_sync(0xffffffffu, h.w, j);
            int k = 4 * j;
            float4 w0 = W2_4[(size_t)(k + 0) * 32 + lane];
            float4 w1 = W2_4[(size_t)(k + 1) * 32 + lane];
            float4 w2 = W2_4[(size_t)(k + 2) * 32 + lane];
            float4 w3 = W2_4[(size_t)(k + 3) * 32 + lane];
            acc.x += hx * w0.x + hy * w1.x + hz * w2.x + hw * w3.x;
            acc.y += hx * w0.y + hy * w1.y + hz * w2.y + hw * w3.y;
            acc.z += hx * w0.z + hy * w1.z + hz * w2.z + hw * w3.z;
            acc.w += hx * w0.w + hy * w1.w + hz * w2.w + hw * w3.w;
        }
        z = acc;
    }
    float m = fmaxf(fmaxf(z.x, z.y), fmaxf(z.z, z.w));
    #pragma unroll
    for (int o = 16; o > 0; o >>= 1) m = fmaxf(m, __shfl_xor_sync(0xffffffffu, m, o));
    float s = __expf(z.x - m) + __expf(z.y - m) + __expf(z.z - m) + __expf(z.w - m);
    #pragma unroll
    for (int o = 16; o > 0; o >>= 1) s += __shfl_xor_sync(0xffffffffu, s, o);
    float ls = m + __logf(s);
    out4[(size_t)i * 32 + lane] = make_float4(z.x - ls, z.y - ls, z.z - ls, z.w - ls);
}

// ---------------- launch ----------------
extern "C" void kernel_launch(void* const* d_in, const int* in_sizes, int n_in,
                              void* d_out, int out_size)
{
    const float* x  = (const float*)d_in[0];
    const float* W1 = (const float*)d_in[1];
    const float* b1 = (const float*)d_in[2];
    const float* W2 = (const float*)d_in[3];
    const float* b2 = (const float*)d_in[4];
    float* out = (float*)d_out;

    float *Y, *G; __half *Hh, *W1h, *W2h;
    cudaGetSymbolAddress((void**)&Y,   g_Y);
    cudaGetSymbolAddress((void**)&G,   g_G);
    cudaGetSymbolAddress((void**)&Hh,  g_Hh);
    cudaGetSymbolAddress((void**)&W1h, g_W1h);
    cudaGetSymbolAddress((void**)&W2h, g_W2h);

    // transpose + fp16-convert weights (K-major)
    transpose_w_h_kernel<<<dim3(EMSIZE / 32, NCLASS / 32, TAPS), dim3(32, 8)>>>(W1, W1h, EMSIZE, NCLASS);
    transpose_w_h_kernel<<<dim3(NCLASS / 32, NCLASS / 32, TAPS), dim3(32, 8)>>>(W2, W2h, NCLASS, NCLASS);

    // K1: Y = x @ W1, 1-D grid, tap = bid%3 -> A tiles L2-shared across taps
    gemm_fp16_kernel<false><<<(N_SENT / 128) * TAPS, 256>>>(x, W1h, Y, EMSIZE);

    // K2: H = tanh(shifted sum + cnt*b1) -> fp16
    combine_tanh_kernel<<<(N_SENT * 32) / 256, 256>>>(
        (const float4*)Y, (const float4*)b1, (uint2*)Hh);

    // K3: G = H @ W2, same remap
    gemm_fp16_kernel<true><<<(N_SENT / 128) * TAPS, 256>>>(Hh, W2h, G, NCLASS);

    // K4: Z combine + fallback + log_softmax
    stage2_softmax_kernel<<<N_SENT / 8, 256>>>(
        (const float4*)G, (const float4*)Y, (const float4*)W2,
        (const float4*)b1, (const float4*)b2, (float4*)out);
}

// round 7
// speedup vs baseline: 1.7832x; 1.0522x over previous
#include <cuda_runtime.h>
#include <cuda_fp16.h>
#include <cstdint>
#include <cstddef>

#define N_SENT 32768
#define EMSIZE 2048
#define NCLASS 128
#define NCOLS  384   // 3 taps * 128
#define TAPS   3

// ---------------- scratch (allocation-free) ----------------
__device__ float  g_Y[(size_t)N_SENT * NCOLS];
__device__ float  g_G[(size_t)N_SENT * NCOLS];
__device__ __half g_Hh[(size_t)N_SENT * NCLASS];
__device__ __half g_W1h[(size_t)TAPS * NCLASS * EMSIZE];   // [tap][c][e] K-major fp16
__device__ __half g_W2h[(size_t)TAPS * NCLASS * NCLASS];   // [tap][c][k] K-major fp16

// ---------------- PTX helpers ----------------
__device__ __forceinline__ uint32_t smem_u32(const void* p) {
    uint32_t a;
    asm("{ .reg .u64 t; cvta.to.shared.u64 t, %1; cvt.u32.u64 %0, t; }" : "=r"(a) : "l"(p));
    return a;
}
__device__ __forceinline__ void cp_async16(uint32_t saddr, const void* g) {
    asm volatile("cp.async.ca.shared.global [%0], [%1], 16;" :: "r"(saddr), "l"(g));
}
__device__ __forceinline__ void cp_commit() {
    asm volatile("cp.async.commit_group;" ::: "memory");
}
template<int n> __device__ __forceinline__ void cp_wait() {
    asm volatile("cp.async.wait_group %0;" :: "n"(n) : "memory");
}
__device__ __forceinline__ void ldsm4(uint32_t r[4], uint32_t saddr) {
    asm volatile("ldmatrix.sync.aligned.m8n8.x4.shared.b16 {%0,%1,%2,%3}, [%4];"
                 : "=r"(r[0]), "=r"(r[1]), "=r"(r[2]), "=r"(r[3]) : "r"(saddr));
}
__device__ __forceinline__ void mma16816(float d[4], const uint32_t a[4], const uint32_t b[2]) {
    asm volatile(
        "mma.sync.aligned.m16n8k16.row.col.f32.f16.f16.f32 "
        "{%0,%1,%2,%3},{%4,%5,%6,%7},{%8,%9},{%0,%1,%2,%3};"
        : "+f"(d[0]), "+f"(d[1]), "+f"(d[2]), "+f"(d[3])
        : "r"(a[0]), "r"(a[1]), "r"(a[2]), "r"(a[3]), "r"(b[0]), "r"(b[1]));
}

// Swizzled 16B-chunk offset inside a 128-row x 32-half (64B/row) tile.
__device__ __forceinline__ uint32_t tile_off(int row, int c) {
    return (uint32_t)(row * 64 + ((c ^ ((row >> 1) & 3)) << 4));
}

#define STAGE_BYTES 16384     // A tile 8KB + B tile 8KB
#define NSTAGES     4
#define SMEM_BYTES  (STAGE_BYTES * NSTAGES)   // 64 KB dynamic

// ---------------- fp16 tensor-core GEMM (4-stage pipeline, 1 sync/iter) ----------------
// Grid: 1-D, bid -> (m_tile = bid/3, tap = bid%3).
template<bool AHALF>
__global__ void __launch_bounds__(256)
gemm_fp16_kernel(const void* __restrict__ Ag,
                 const __half* __restrict__ Bg,
                 float* __restrict__ C,
                 int K)
{
    extern __shared__ __align__(128) uint8_t dsm[];

    const int tid  = threadIdx.x;
    const int lane = tid & 31;
    const int warp = tid >> 5;
    const int wm   = warp >> 1;   // 0..3
    const int wn   = warp & 1;    // 0..1
    const int tap  = blockIdx.x % TAPS;
    const int m0   = (blockIdx.x / TAPS) * 128;
    const __half* Bt = Bg + (size_t)tap * 128 * K;
    const int KT = K >> 5;

    const int lrow = tid >> 2;       // 0..63 (second chunk at +64)
    const int lc   = tid & 3;
    const uint32_t soff1 = tile_off(lrow, lc);
    const uint32_t soff2 = soff1 + 64 * 64;

    const uint32_t sbase = smem_u32(dsm);
    uint32_t aoff[2][2], boff[4][2];
    {
        const int arow0 = wm * 32 + (lane & 7) + 8 * ((lane >> 3) & 1);
        const int acadd = lane >> 4;
        const int brow0 = wn * 64 + (lane & 7) + 8 * (lane >> 4);
        const int bcadd = (lane >> 3) & 1;
        #pragma unroll
        for (int kk = 0; kk < 2; kk++) {
            #pragma unroll
            for (int mi = 0; mi < 2; mi++)
                aoff[mi][kk] = tile_off(arow0 + mi * 16, kk * 2 + acadd);
            #pragma unroll
            for (int nip = 0; nip < 4; nip++)
                boff[nip][kk] = tile_off(brow0 + nip * 16, kk * 2 + bcadd);
        }
    }

    float acc[2][8][4];
    #pragma unroll
    for (int mi = 0; mi < 2; mi++)
        #pragma unroll
        for (int ni = 0; ni < 8; ni++)
            #pragma unroll
            for (int q = 0; q < 4; q++) acc[mi][ni][q] = 0.f;

    const float*  Af = (const float*)Ag;
    const __half* Ah = (const __half*)Ag;
    __half2 st[8];   // staged converted A chunk (for !AHALF), holds chunk kt at iter kt

    // ---- prologue: stages 0 and 1 ----
    #pragma unroll
    for (int s = 0; s < 2; s++) {
        const uint32_t sp = sbase + s * STAGE_BYTES;
        const int kb = s << 5;
        if (AHALF) {
            cp_async16(sp + soff1, Ah + (size_t)(m0 + lrow) * K + kb + lc * 8);
            cp_async16(sp + soff2, Ah + (size_t)(m0 + lrow + 64) * K + kb + lc * 8);
        }
        cp_async16(sp + 8192 + soff1, Bt + (size_t)lrow * K + kb + lc * 8);
        cp_async16(sp + 8192 + soff2, Bt + (size_t)(lrow + 64) * K + kb + lc * 8);
        cp_commit();
    }
    if (!AHALF) {
        const float* p1 = Af + (size_t)(m0 + lrow) * K + lc * 8;
        const float* p2 = Af + (size_t)(m0 + lrow + 64) * K + lc * 8;
        float4 v0 = *(const float4*)p1, v1 = *(const float4*)(p1 + 4);
        float4 w0 = *(const float4*)p2, w1 = *(const float4*)(p2 + 4);
        st[0] = __floats2half2_rn(v0.x, v0.y); st[1] = __floats2half2_rn(v0.z, v0.w);
        st[2] = __floats2half2_rn(v1.x, v1.y); st[3] = __floats2half2_rn(v1.z, v1.w);
        st[4] = __floats2half2_rn(w0.x, w0.y); st[5] = __floats2half2_rn(w0.z, w0.w);
        st[6] = __floats2half2_rn(w1.x, w1.y); st[7] = __floats2half2_rn(w1.z, w1.w);
    }

    for (int kt = 0; kt < KT; kt++) {
        const uint32_t sbuf = sbase + (uint32_t)(kt & 3) * STAGE_BYTES;

        // store this iteration's converted A chunk (writes stage kt; safe vs reads of kt-1/kt... A-area only)
        if (!AHALF) {
            *(uint4*)(dsm + (kt & 3) * STAGE_BYTES + soff1) = *(uint4*)(&st[0]);
            *(uint4*)(dsm + (kt & 3) * STAGE_BYTES + soff2) = *(uint4*)(&st[4]);
        }

        // prefetch chunk kt+2 into stage (kt+2)&3
        if (kt + 2 < KT) {
            const int kb = (kt + 2) << 5;
            const uint32_t sp = sbase + (uint32_t)((kt + 2) & 3) * STAGE_BYTES;
            if (AHALF) {
                cp_async16(sp + soff1, Ah + (size_t)(m0 + lrow) * K + kb + lc * 8);
                cp_async16(sp + soff2, Ah + (size_t)(m0 + lrow + 64) * K + kb + lc * 8);
            }
            cp_async16(sp + 8192 + soff1, Bt + (size_t)lrow * K + kb + lc * 8);
            cp_async16(sp + 8192 + soff2, Bt + (size_t)(lrow + 64) * K + kb + lc * 8);
            cp_commit();
        }

        // LDG+convert A chunk kt+1 into registers (overlaps with compute)
        if (!AHALF && kt + 1 < KT) {
            const int kb = (kt + 1) << 5;
            const float* p1 = Af + (size_t)(m0 + lrow) * K + kb + lc * 8;
            const float* p2 = Af + (size_t)(m0 + lrow + 64) * K + kb + lc * 8;
            float4 v0 = *(const float4*)p1, v1 = *(const float4*)(p1 + 4);
            float4 w0 = *(const float4*)p2, w1 = *(const float4*)(p2 + 4);
            st[0] = __floats2half2_rn(v0.x, v0.y); st[1] = __floats2half2_rn(v0.z, v0.w);
            st[2] = __floats2half2_rn(v1.x, v1.y); st[3] = __floats2half2_rn(v1.z, v1.w);
            st[4] = __floats2half2_rn(w0.x, w0.y); st[5] = __floats2half2_rn(w0.z, w0.w);
            st[6] = __floats2half2_rn(w1.x, w1.y); st[7] = __floats2half2_rn(w1.z, w1.w);
        }

        // ensure chunk kt's cp.async group completed (≤2 newer groups outstanding)
        if      (kt + 2 < KT) cp_wait<2>();
        else if (kt + 1 < KT) cp_wait<1>();
        else                  cp_wait<0>();
        __syncthreads();   // single barrier per iteration

        #pragma unroll
        for (int kk = 0; kk < 2; kk++) {
            uint32_t a[2][4], b[4][4];
            #pragma unroll
            for (int mi = 0; mi < 2; mi++) ldsm4(a[mi], sbuf + aoff[mi][kk]);
            #pragma unroll
            for (int nip = 0; nip < 4; nip++) ldsm4(b[nip], sbuf + 8192 + boff[nip][kk]);
            #pragma unroll
            for (int mi = 0; mi < 2; mi++)
                #pragma unroll
                for (int ni = 0; ni < 8; ni++)
                    mma16816(acc[mi][ni], a[mi], &b[ni >> 1][(ni & 1) * 2]);
        }
        // no trailing barrier: next iter writes stages kt+1 (STS) / kt+3 (cp.async),
        // never stage kt or kt-1 with NSTAGES=4
    }

    // epilogue
    const int gid = lane >> 2, tig = lane & 3;
    #pragma unroll
    for (int mi = 0; mi < 2; mi++) {
        const int r0 = m0 + wm * 32 + mi * 16 + gid;
        #pragma unroll
        for (int ni = 0; ni < 8; ni++) {
            const int col = tap * 128 + wn * 64 + ni * 8 + tig * 2;
            *(float2*)&C[(size_t)r0 * NCOLS + col]       = make_float2(acc[mi][ni][0], acc[mi][ni][1]);
            *(float2*)&C[(size_t)(r0 + 8) * NCOLS + col] = make_float2(acc[mi][ni][2], acc[mi][ni][3]);
        }
    }
}

// ---------------- weight transpose + fp16 convert ----------------
__global__ void transpose_w_h_kernel(const float* __restrict__ W, __half* __restrict__ Wt,
                                     int E, int C)
{
    __shared__ float tile[32][33];
    const int t  = blockIdx.z;
    const int e0 = blockIdx.x << 5, c0 = blockIdx.y << 5;
    const float* src = W + (size_t)t * E * C;
    __half* dst = Wt + (size_t)t * C * E;
    #pragma unroll
    for (int j = 0; j < 32; j += 8)
        tile[threadIdx.y + j][threadIdx.x] =
            src[(size_t)(e0 + threadIdx.y + j) * C + c0 + threadIdx.x];
    __syncthreads();
    #pragma unroll
    for (int j = 0; j < 32; j += 8)
        dst[(size_t)(c0 + threadIdx.y + j) * E + e0 + threadIdx.x] =
            __float2half_rn(tile[threadIdx.x][threadIdx.y + j]);
}

// ---------------- combine + tanh -> fp16 H ----------------
__global__ void combine_tanh_kernel(const float4* __restrict__ Y4,
                                    const float4* __restrict__ b1_4,
                                    uint2* __restrict__ H2)
{
    int idx = blockIdx.x * blockDim.x + threadIdx.x;   // < N_SENT*32
    int p = idx >> 5, q = idx & 31;
    float4 s = Y4[(size_t)p * 96 + q];
    float cnt = 1.f;
    if (p >= 1) { float4 a = Y4[(size_t)(p - 1) * 96 + 32 + q];
                  s.x += a.x; s.y += a.y; s.z += a.z; s.w += a.w; cnt = 2.f; }
    if (p >= 2) { float4 a = Y4[(size_t)(p - 2) * 96 + 64 + q];
                  s.x += a.x; s.y += a.y; s.z += a.z; s.w += a.w; cnt = 3.f; }
    float4 b = b1_4[q];
    __half2 h01 = __floats2half2_rn(tanhf(s.x + cnt * b.x), tanhf(s.y + cnt * b.y));
    __half2 h23 = __floats2half2_rn(tanhf(s.z + cnt * b.z), tanhf(s.w + cnt * b.w));
    uint2 u;
    u.x = *reinterpret_cast<uint32_t*>(&h01);
    u.y = *reinterpret_cast<uint32_t*>(&h23);
    H2[(size_t)p * 32 + q] = u;
}

// ---------------- stage-2 combine + fallback + log_softmax (warp/row) ----------------
__global__ void stage2_softmax_kernel(const float4* __restrict__ G4,
                                      const float4* __restrict__ Y4,
                                      const float4* __restrict__ W2_4,
                                      const float4* __restrict__ b1_4,
                                      const float4* __restrict__ b2_4,
                                      float4* __restrict__ out4)
{
    const int warp = threadIdx.x >> 5, lane = threadIdx.x & 31;
    const int i = blockIdx.x * 8 + warp;
    float4 z;
    if (i >= 2) {
        float4 a = G4[(size_t)(i - 2) * 96 + lane];
        float4 b = G4[(size_t)(i - 1) * 96 + 32 + lane];
        float4 c = G4[(size_t)i * 96 + 64 + lane];
        float4 bb = b2_4[lane];
        z.x = a.x + b.x + c.x + 3.f * bb.x;
        z.y = a.y + b.y + c.y + 3.f * bb.y;
        z.z = a.z + b.z + c.z + 3.f * bb.z;
        z.w = a.w + b.w + c.w + 3.f * bb.w;
    } else {
        float4 y = Y4[(size_t)i * 96 + lane];
        float4 b1v = b1_4[lane];
        float4 h;
        h.x = tanhf(y.x + b1v.x); h.y = tanhf(y.y + b1v.y);
        h.z = tanhf(y.z + b1v.z); h.w = tanhf(y.w + b1v.w);
        float4 acc = b2_4[lane];
        for (int j = 0; j < 32; j++) {
            float hx = __shfl_sync(0xffffffffu, h.x, j);
            float hy = __shfl_sync(0xffffffffu, h.y, j);
            float hz = __shfl_sync(0xffffffffu, h.z, j);
            float hw = __shfl_sync(0xffffffffu, h.w, j);
            int k = 4 * j;
            float4 w0 = W2_4[(size_t)(k + 0) * 32 + lane];
            float4 w1 = W2_4[(size_t)(k + 1) * 32 + lane];
            float4 w2 = W2_4[(size_t)(k + 2) * 32 + lane];
            float4 w3 = W2_4[(size_t)(k + 3) * 32 + lane];
            acc.x += hx * w0.x + hy * w1.x + hz * w2.x + hw * w3.x;
            acc.y += hx * w0.y + hy * w1.y + hz * w2.y + hw * w3.y;
            acc.z += hx * w0.z + hy * w1.z + hz * w2.z + hw * w3.z;
            acc.w += hx * w0.w + hy * w1.w + hz * w2.w + hw * w3.w;
        }
        z = acc;
    }
    float m = fmaxf(fmaxf(z.x, z.y), fmaxf(z.z, z.w));
    #pragma unroll
    for (int o = 16; o > 0; o >>= 1) m = fmaxf(m, __shfl_xor_sync(0xffffffffu, m, o));
    float s = __expf(z.x - m) + __expf(z.y - m) + __expf(z.z - m) + __expf(z.w - m);
    #pragma unroll
    for (int o = 16; o > 0; o >>= 1) s += __shfl_xor_sync(0xffffffffu, s, o);
    float ls = m + __logf(s);
    out4[(size_t)i * 32 + lane] = make_float4(z.x - ls, z.y - ls, z.z - ls, z.w - ls);
}

// ---------------- launch ----------------
extern "C" void kernel_launch(void* const* d_in, const int* in_sizes, int n_in,
                              void* d_out, int out_size)
{
    const float* x  = (const float*)d_in[0];
    const float* W1 = (const float*)d_in[1];
    const float* b1 = (const float*)d_in[2];
    const float* W2 = (const float*)d_in[3];
    const float* b2 = (const float*)d_in[4];
    float* out = (float*)d_out;

    float *Y, *G; __half *Hh, *W1h, *W2h;
    cudaGetSymbolAddress((void**)&Y,   g_Y);
    cudaGetSymbolAddress((void**)&G,   g_G);
    cudaGetSymbolAddress((void**)&Hh,  g_Hh);
    cudaGetSymbolAddress((void**)&W1h, g_W1h);
    cudaGetSymbolAddress((void**)&W2h, g_W2h);

    static bool attr_done = false;
    if (!attr_done) {
        cudaFuncSetAttribute(gemm_fp16_kernel<false>,
                             cudaFuncAttributeMaxDynamicSharedMemorySize, SMEM_BYTES);
        cudaFuncSetAttribute(gemm_fp16_kernel<true>,
                             cudaFuncAttributeMaxDynamicSharedMemorySize, SMEM_BYTES);
        attr_done = true;
    }

    // transpose + fp16-convert weights (K-major)
    transpose_w_h_kernel<<<dim3(EMSIZE / 32, NCLASS / 32, TAPS), dim3(32, 8)>>>(W1, W1h, EMSIZE, NCLASS);
    transpose_w_h_kernel<<<dim3(NCLASS / 32, NCLASS / 32, TAPS), dim3(32, 8)>>>(W2, W2h, NCLASS, NCLASS);

    // K1: Y = x @ W1, tap = bid%3 (A tiles L2-shared across taps)
    gemm_fp16_kernel<false><<<(N_SENT / 128) * TAPS, 256, SMEM_BYTES>>>(x, W1h, Y, EMSIZE);

    // K2: H = tanh(shifted sum + cnt*b1) -> fp16
    combine_tanh_kernel<<<(N_SENT * 32) / 256, 256>>>(
        (const float4*)Y, (const float4*)b1, (uint2*)Hh);

    // K3: G = H @ W2
    gemm_fp16_kernel<true><<<(N_SENT / 128) * TAPS, 256, SMEM_BYTES>>>(Hh, W2h, G, NCLASS);

    // K4: Z combine + fallback + log_softmax
    stage2_softmax_kernel<<<N_SENT / 8, 256>>>(
        (const float4*)G, (const float4*)Y, (const float4*)W2,
        (const float4*)b1, (const float4*)b2, (float4*)out);
}